// round 5
// baseline (speedup 1.0000x reference)
#include <cuda_runtime.h>
#include <cstdint>

#define B_DIM 512
#define D_DIM 256
#define C_DIM 100000
#define BM 128
#define BN 128
#define BK 16
#define NKT (D_DIM / BK)   // 16 K-tiles

// Scratch (no cudaMalloc allowed anywhere)
__device__ float g_winv[C_DIM];   // 1/||w_c||
__device__ float g_xlen[B_DIM];   // ||x_b||
__device__ float g_xinv[B_DIM];   // 1/||x_b||

// ---------------------------------------------------------------------------
// Fused norm prepass: one warp per row (256 floats = 2 float4/lane).
// Blocks [0, W_BLOCKS) handle w rows; blocks [W_BLOCKS, +X_BLOCKS) handle x.
// ---------------------------------------------------------------------------
#define W_BLOCKS ((C_DIM + 7) / 8)          // 12500
#define X_BLOCKS ((B_DIM + 7) / 8)          // 64

__global__ void norms_kernel(const float* __restrict__ w,
                             const float* __restrict__ x) {
    int lane = threadIdx.x & 31;
    int wslot = (blockIdx.x * blockDim.x + threadIdx.x) >> 5;
    bool is_w = blockIdx.x < W_BLOCKS;
    int row = is_w ? wslot : (wslot - W_BLOCKS * 8);
    int nrows = is_w ? C_DIM : B_DIM;
    if (row >= nrows) return;
    const float* base = is_w ? (w + (size_t)row * D_DIM)
                             : (x + (size_t)row * D_DIM);
    const float4* p = reinterpret_cast<const float4*>(base);
    float4 v0 = p[lane];
    float4 v1 = p[lane + 32];
    float s = v0.x*v0.x + v0.y*v0.y + v0.z*v0.z + v0.w*v0.w
            + v1.x*v1.x + v1.y*v1.y + v1.z*v1.z + v1.w*v1.w;
    #pragma unroll
    for (int o = 16; o > 0; o >>= 1) s += __shfl_xor_sync(0xffffffffu, s, o);
    if (lane == 0) {
        if (is_w) {
            g_winv[row] = rsqrtf(s);
        } else {
            float sq = sqrtf(s);
            g_xlen[row] = sq;
            g_xinv[row] = 1.0f / sq;
        }
    }
}

// ---------------------------------------------------------------------------
// f32x2 helpers (FFMA2 — full-rate fp32 on sm_103a; plain 3-reg FFMA is
// half rate per SASS_QUICKREF; fma.rn.f32x2 is the only route from C++).
// ---------------------------------------------------------------------------
__device__ __forceinline__ unsigned long long pack_dup_f32(float a) {
    unsigned long long r;
    unsigned int ai = __float_as_uint(a);
    asm("mov.b64 %0, {%1, %1};" : "=l"(r) : "r"(ai));
    return r;
}
__device__ __forceinline__ void fma_f32x2(unsigned long long& d,
                                          unsigned long long a,
                                          unsigned long long b) {
    asm("fma.rn.f32x2 %0, %1, %2, %3;" : "=l"(d) : "l"(a), "l"(b), "l"(d));
}
__device__ __forceinline__ void unpack_f32x2(unsigned long long v, float& lo, float& hi) {
    unsigned int l, h;
    asm("mov.b64 {%0, %1}, %2;" : "=r"(l), "=r"(h) : "l"(v));
    lo = __uint_as_float(l);
    hi = __uint_as_float(h);
}

// ---------------------------------------------------------------------------
// GEMM + epilogue: out[b,c] = clip(dot(x_b,w_c)*winv_c*xinv_b, -1,1)*xlen_b
// 128x128x16 tile, 256 threads, 8x8 microtile, f32x2 accumulators.
// Register double-buffering hides ~600-cyc LDG latency behind ~1024 cyc of
// FMA per tile. Epilogue scale loads are hoisted into the final k-tile's
// (otherwise empty) prefetch slot. blockIdx.x = M-tile (fast dim): 4 CTAs
// sharing a weight tile co-reside -> weight from L2, x (512 KB) L2-resident.
// ---------------------------------------------------------------------------
__global__ __launch_bounds__(256, 2)
void angle_gemm_kernel(const float* __restrict__ x,
                       const float* __restrict__ w,
                       float* __restrict__ out) {
    __shared__ __align__(16) float As[2][BK][BM];
    __shared__ __align__(16) float Bs[2][BK][BN];

    const int tid = threadIdx.x;
    const int tx  = tid & 15;          // N micro index (8 cols)
    const int ty  = tid >> 4;          // M micro index (8 rows)
    const int m0  = blockIdx.x * BM;
    const int n0  = blockIdx.y * BN;

    // Load coords: 2 fragments/thread. fragment f in [0,512):
    //   row = f>>2 (0..127), kq = (f&3)*4 (0,4,8,12)
    const int r0  = tid >> 2;          // rows 0..63
    const int kq0 = (tid & 3) * 4;
    const int r1  = r0 + 64;           // rows 64..127

    const bool bok0 = (n0 + r0) < C_DIM;
    const bool bok1 = (n0 + r1) < C_DIM;

    const float* xa0 = x + (size_t)(m0 + r0) * D_DIM + kq0;
    const float* xa1 = x + (size_t)(m0 + r1) * D_DIM + kq0;
    const float* wb0 = w + (size_t)(n0 + r0) * D_DIM + kq0;
    const float* wb1 = w + (size_t)(n0 + r1) * D_DIM + kq0;

    unsigned long long acc[8][4];
    #pragma unroll
    for (int i = 0; i < 8; i++)
        #pragma unroll
        for (int j = 0; j < 4; j++) acc[i][j] = 0ull;

    // ---- prologue: tile 0 -> regs -> smem buffer 0 ----
    float4 avr[2], bvr[2];
    avr[0] = *reinterpret_cast<const float4*>(xa0);
    avr[1] = *reinterpret_cast<const float4*>(xa1);
    bvr[0] = bok0 ? *reinterpret_cast<const float4*>(wb0)
                  : make_float4(0.f, 0.f, 0.f, 0.f);
    bvr[1] = bok1 ? *reinterpret_cast<const float4*>(wb1)
                  : make_float4(0.f, 0.f, 0.f, 0.f);

    int buf = 0;
    As[0][kq0 + 0][r0] = avr[0].x; As[0][kq0 + 1][r0] = avr[0].y;
    As[0][kq0 + 2][r0] = avr[0].z; As[0][kq0 + 3][r0] = avr[0].w;
    As[0][kq0 + 0][r1] = avr[1].x; As[0][kq0 + 1][r1] = avr[1].y;
    As[0][kq0 + 2][r1] = avr[1].z; As[0][kq0 + 3][r1] = avr[1].w;
    Bs[0][kq0 + 0][r0] = bvr[0].x; Bs[0][kq0 + 1][r0] = bvr[0].y;
    Bs[0][kq0 + 2][r0] = bvr[0].z; Bs[0][kq0 + 3][r0] = bvr[0].w;
    Bs[0][kq0 + 0][r1] = bvr[1].x; Bs[0][kq0 + 1][r1] = bvr[1].y;
    Bs[0][kq0 + 2][r1] = bvr[1].z; Bs[0][kq0 + 3][r1] = bvr[1].w;
    __syncthreads();

    float wv[8], xl, xi;               // epilogue scales, loaded early

    for (int kt = 0; kt < NKT; kt++) {
        const bool have_next = (kt + 1) < NKT;
        if (have_next) {
            const int kb = (kt + 1) * BK;
            avr[0] = *reinterpret_cast<const float4*>(xa0 + kb);
            avr[1] = *reinterpret_cast<const float4*>(xa1 + kb);
            bvr[0] = bok0 ? *reinterpret_cast<const float4*>(wb0 + kb)
                          : make_float4(0.f, 0.f, 0.f, 0.f);
            bvr[1] = bok1 ? *reinterpret_cast<const float4*>(wb1 + kb)
                          : make_float4(0.f, 0.f, 0.f, 0.f);
        } else {
            // Final tile: prefetch slot is free — issue epilogue scale loads
            // here so their latency hides behind the last compute block.
            #pragma unroll
            for (int j = 0; j < 8; j++) {
                int gn = n0 + tx * 8 + j;
                wv[j] = (gn < C_DIM) ? __ldg(&g_winv[gn]) : 0.f;
            }
            xl = __ldg(&g_xlen[m0 + ty * 8]);   // row 0 of microtile; rest below
            xi = __ldg(&g_xinv[m0 + ty * 8]);
        }

        // Compute on current buffer (A: 2x LDS.128, B: 2x LDS.128 per k)
        #pragma unroll
        for (int k = 0; k < BK; k++) {
            float4 a0 = *reinterpret_cast<const float4*>(&As[buf][k][ty * 8]);
            float4 a1 = *reinterpret_cast<const float4*>(&As[buf][k][ty * 8 + 4]);
            float af[8] = {a0.x, a0.y, a0.z, a0.w, a1.x, a1.y, a1.z, a1.w};
            float4 b0 = *reinterpret_cast<const float4*>(&Bs[buf][k][tx * 8]);
            float4 b1 = *reinterpret_cast<const float4*>(&Bs[buf][k][tx * 8 + 4]);
            unsigned long long bp[4];
            bp[0] = *reinterpret_cast<const unsigned long long*>(&b0.x);
            bp[1] = *reinterpret_cast<const unsigned long long*>(&b0.z);
            bp[2] = *reinterpret_cast<const unsigned long long*>(&b1.x);
            bp[3] = *reinterpret_cast<const unsigned long long*>(&b1.z);
            #pragma unroll
            for (int i = 0; i < 8; i++) {
                unsigned long long ap = pack_dup_f32(af[i]);
                #pragma unroll
                for (int j = 0; j < 4; j++) fma_f32x2(acc[i][j], ap, bp[j]);
            }
        }

        if (have_next) {
            int nb = buf ^ 1;
            As[nb][kq0 + 0][r0] = avr[0].x; As[nb][kq0 + 1][r0] = avr[0].y;
            As[nb][kq0 + 2][r0] = avr[0].z; As[nb][kq0 + 3][r0] = avr[0].w;
            As[nb][kq0 + 0][r1] = avr[1].x; As[nb][kq0 + 1][r1] = avr[1].y;
            As[nb][kq0 + 2][r1] = avr[1].z; As[nb][kq0 + 3][r1] = avr[1].w;
            Bs[nb][kq0 + 0][r0] = bvr[0].x; Bs[nb][kq0 + 1][r0] = bvr[0].y;
            Bs[nb][kq0 + 2][r0] = bvr[0].z; Bs[nb][kq0 + 3][r0] = bvr[0].w;
            Bs[nb][kq0 + 0][r1] = bvr[1].x; Bs[nb][kq0 + 1][r1] = bvr[1].y;
            Bs[nb][kq0 + 2][r1] = bvr[1].z; Bs[nb][kq0 + 3][r1] = bvr[1].w;
            __syncthreads();
            buf = nb;
        }
    }

    // Epilogue: scale by winv[c]*xinv[b], clip, rescale by xlen[b]
    #pragma unroll
    for (int i = 0; i < 8; i++) {
        int m = m0 + ty * 8 + i;
        float xli = (i == 0) ? xl : __ldg(&g_xlen[m]);
        float xii = (i == 0) ? xi : __ldg(&g_xinv[m]);
        float r[8];
        #pragma unroll
        for (int j = 0; j < 4; j++) unpack_f32x2(acc[i][j], r[2 * j], r[2 * j + 1]);
        #pragma unroll
        for (int j = 0; j < 8; j++) {
            float cosv = fminf(1.f, fmaxf(-1.f, r[j] * wv[j] * xii));
            r[j] = cosv * xli;
        }
        int gn = n0 + tx * 8;
        float* po = out + (size_t)m * C_DIM + gn;
        if (gn + 7 < C_DIM) {
            *reinterpret_cast<float4*>(po)     = make_float4(r[0], r[1], r[2], r[3]);
            *reinterpret_cast<float4*>(po + 4) = make_float4(r[4], r[5], r[6], r[7]);
        } else {
            #pragma unroll
            for (int j = 0; j < 8; j++)
                if (gn + j < C_DIM) po[j] = r[j];
        }
    }
}

// ---------------------------------------------------------------------------
// Margin fix-up at label positions only (512 elements)
// ---------------------------------------------------------------------------
__global__ void fixup_kernel(const int* __restrict__ y, float* __restrict__ out) {
    int b = blockIdx.x * blockDim.x + threadIdx.x;
    if (b >= B_DIM) return;
    int c = y[b];
    float xl   = g_xlen[b];
    size_t idx = (size_t)b * C_DIM + c;
    float feat = out[idx];
    float cosv = fminf(1.f, fmaxf(-1.f, feat / xl));
    float c2   = cosv * cosv;
    float cosm = 8.f * c2 * c2 - 8.f * c2 + 1.f;                   // cos(4t)
    float kf   = floorf(4.f * acosf(cosv) * 0.3183098861837907f);  // floor(4t/pi)
    float sign = (((int)kf) & 1) ? -1.f : 1.f;
    float phi  = sign * cosm - 2.f * kf;
    out[idx]   = feat + (phi * xl - feat) * (1.f / 1001.f);
}

// ---------------------------------------------------------------------------
extern "C" void kernel_launch(void* const* d_in, const int* in_sizes, int n_in,
                              void* d_out, int out_size) {
    const float* x = (const float*)d_in[0];   // (512, 256)
    const float* w = (const float*)d_in[1];   // (100000, 256)
    const int*   y = (const int*)d_in[2];     // (512,)
    float* out = (float*)d_out;               // (512, 100000)

    norms_kernel<<<W_BLOCKS + X_BLOCKS, 256>>>(w, x);
    dim3 grid(B_DIM / BM, (C_DIM + BN - 1) / BN);
    angle_gemm_kernel<<<grid, 256>>>(x, w, out);
    fixup_kernel<<<2, 256>>>(y, out);
}

// round 8
// speedup vs baseline: 2.1322x; 2.1322x over previous
#include <cuda_runtime.h>
#include <cuda_bf16.h>
#include <cstdint>

#define B_DIM 512
#define D_DIM 256
#define C_DIM 100000
#define TMB 128
#define TNB 128
#define TKB 32
#define NSTAGE (D_DIM / TKB)          // 8 k-stages
#define NT_N ((C_DIM + TNB - 1) / TNB)  // 782

// ---------------- scratch (static __device__, no allocs) -------------------
__device__ float g_xlen[B_DIM];
__device__ __nv_bfloat16 g_xhi[B_DIM * D_DIM];
__device__ __nv_bfloat16 g_xlo[B_DIM * D_DIM];
__device__ __nv_bfloat16 g_whi[(size_t)C_DIM * D_DIM];
__device__ __nv_bfloat16 g_wlo[(size_t)C_DIM * D_DIM];

// ---------------------------------------------------------------------------
// Prepass: one warp per row; compute norm, normalize, split into bf16 hi+lo.
// Normalized rows => GEMM emits cos(theta) directly (no winv/xinv epilogue).
// ---------------------------------------------------------------------------
#define W_BLOCKS ((C_DIM + 7) / 8)   // 12500
#define X_BLOCKS ((B_DIM + 7) / 8)   // 64

__global__ void prep_kernel(const float* __restrict__ w,
                            const float* __restrict__ x) {
    int lane  = threadIdx.x & 31;
    int wslot = (blockIdx.x * blockDim.x + threadIdx.x) >> 5;
    bool is_w = blockIdx.x < W_BLOCKS;
    int row   = is_w ? wslot : (wslot - W_BLOCKS * 8);
    int nrows = is_w ? C_DIM : B_DIM;
    if (row >= nrows) return;

    const float* base = is_w ? (w + (size_t)row * D_DIM)
                             : (x + (size_t)row * D_DIM);
    const float4* p = reinterpret_cast<const float4*>(base);
    float4 v0 = p[lane];
    float4 v1 = p[lane + 32];
    float s = v0.x*v0.x + v0.y*v0.y + v0.z*v0.z + v0.w*v0.w
            + v1.x*v1.x + v1.y*v1.y + v1.z*v1.z + v1.w*v1.w;
    #pragma unroll
    for (int o = 16; o > 0; o >>= 1) s += __shfl_xor_sync(0xffffffffu, s, o);

    float rinv = rsqrtf(s);
    if (!is_w && lane == 0) g_xlen[row] = sqrtf(s);

    __nv_bfloat16* hi = is_w ? g_whi : g_xhi;
    __nv_bfloat16* lo = is_w ? g_wlo : g_xlo;
    size_t rb = (size_t)row * D_DIM;
    float vals[8] = {v0.x, v0.y, v0.z, v0.w, v1.x, v1.y, v1.z, v1.w};
    int   cols[8] = {lane*4, lane*4+1, lane*4+2, lane*4+3,
                     (lane+32)*4, (lane+32)*4+1, (lane+32)*4+2, (lane+32)*4+3};
    #pragma unroll
    for (int i = 0; i < 8; i++) {
        float v = vals[i] * rinv;
        __nv_bfloat16 h = __float2bfloat16(v);
        __nv_bfloat16 l = __float2bfloat16(v - __bfloat162float(h));
        hi[rb + cols[i]] = h;
        lo[rb + cols[i]] = l;
    }
}

// ---------------------------------------------------------------------------
// Arch-portable tensor path (compute_103-safe): ldmatrix + mma.sync bf16.
// ---------------------------------------------------------------------------
__device__ __forceinline__ uint32_t smem_u32(const void* p) {
    uint32_t a;
    asm("{ .reg .u64 t; cvta.to.shared.u64 t, %1; cvt.u32.u64 %0, t; }"
        : "=r"(a) : "l"(p));
    return a;
}
__device__ __forceinline__ void ldsm4(uint32_t* r, uint32_t addr) {
    asm volatile("ldmatrix.sync.aligned.m8n8.x4.shared.b16 {%0,%1,%2,%3}, [%4];"
                 : "=r"(r[0]), "=r"(r[1]), "=r"(r[2]), "=r"(r[3]) : "r"(addr));
}
__device__ __forceinline__ void mma16816(float* c, const uint32_t* a,
                                         uint32_t b0, uint32_t b1) {
    asm volatile(
        "mma.sync.aligned.m16n8k16.row.col.f32.bf16.bf16.f32 "
        "{%0,%1,%2,%3}, {%4,%5,%6,%7}, {%8,%9}, {%0,%1,%2,%3};"
        : "+f"(c[0]), "+f"(c[1]), "+f"(c[2]), "+f"(c[3])
        : "r"(a[0]), "r"(a[1]), "r"(a[2]), "r"(a[3]), "r"(b0), "r"(b1));
}
__device__ __forceinline__ void cpa16(uint32_t dst, const void* src, int sz) {
    asm volatile("cp.async.ca.shared.global [%0], [%1], 16, %2;"
                 :: "r"(dst), "l"(src), "r"(sz));
}
#define CP_COMMIT() asm volatile("cp.async.commit_group;" ::: "memory")
#define CP_WAIT(n)  asm volatile("cp.async.wait_group %0;" :: "n"(n) : "memory")

// 64B-row swizzle: phys = row*64 + ((chunk16 ^ ((row>>1)&3)) * 16).
// ldmatrix reads 8 rows/one chunk -> bank groups {c, c^1, c^2, c^3} x two
// 64B halves = 8 distinct 4-bank groups: conflict-free.
__device__ __forceinline__ uint32_t swz64(int row, int chunk) {
    return (uint32_t)(row * 64 + ((chunk ^ ((row >> 1) & 3)) << 4));
}

// SMEM stage layout: Ahi | Alo | Bhi | Blo, each 128 rows x 64B = 8 KB
#define ST_AHI 0
#define ST_ALO 8192
#define ST_BHI 16384
#define ST_BLO 24576
#define ST_SZ  32768
#define SM_TOTAL (2 * ST_SZ)   // 64 KB double-buffered -> 2 CTAs/SM

// ---------------------------------------------------------------------------
// GEMM: cos[b,c] via 3-term bf16 split (ah*bh + ah*bl + al*bh), fp32 acc.
// CTA 128x128x32, 8 warps in 2(M)x4(N), warp tile 64x32, m16n8k16 HMMA.
// cp.async double-buffered stages. Epilogue: clip * xlen.
// ---------------------------------------------------------------------------
__global__ __launch_bounds__(256, 2)
void mma_gemm_kernel(float* __restrict__ out) {
    extern __shared__ char smem[];
    const uint32_t sbase = smem_u32(smem);

    const int tid    = threadIdx.x;
    const int lane   = tid & 31;
    const int wid    = tid >> 5;
    const int warp_m = wid & 1;        // 0..1 -> 64 rows
    const int warp_n = wid >> 1;       // 0..3 -> 32 cols
    const int m0     = blockIdx.x * TMB;   // fast dim: 4 CTAs share B tile in L2
    const int n0     = blockIdx.y * TNB;

    // ---- cp.async store-side mapping: row = tid>>1, two 16B chunks ----
    const int srow = tid >> 1;
    const int sc0  = (tid & 1) * 2;
    const uint32_t d0 = swz64(srow, sc0);
    const uint32_t d1 = swz64(srow, sc0 + 1);
    const size_t axoff = (size_t)(m0 + srow) * D_DIM + sc0 * 8;
    const int gn   = n0 + srow;
    const int bsz  = (gn < C_DIM) ? 16 : 0;      // 0 => cp.async zero-fill
    const size_t bxoff = (size_t)((gn < C_DIM) ? gn : 0) * D_DIM + sc0 * 8;

    // ---- ldmatrix lane mappings (canonical m16n8k16 fragments) ----
    const int a_rl = (lane & 15);            // A: rows m0-15, chunks k0/k8
    const int a_cl = (lane >> 4);
    const int b_rl = (lane & 7) + ((lane >> 4) & 1) * 8;  // B: (n,k) quads
    const int b_cl = (lane >> 3) & 1;

    float acc[4][4][4];
    #pragma unroll
    for (int i = 0; i < 4; i++)
        #pragma unroll
        for (int j = 0; j < 4; j++)
            #pragma unroll
            for (int r = 0; r < 4; r++) acc[i][j][r] = 0.f;

    // ---- prologue: stage 0 ----
    {
        uint32_t b = sbase;
        cpa16(b + ST_AHI + d0, g_xhi + axoff,     16);
        cpa16(b + ST_AHI + d1, g_xhi + axoff + 8, 16);
        cpa16(b + ST_ALO + d0, g_xlo + axoff,     16);
        cpa16(b + ST_ALO + d1, g_xlo + axoff + 8, 16);
        cpa16(b + ST_BHI + d0, g_whi + bxoff,     bsz);
        cpa16(b + ST_BHI + d1, g_whi + bxoff + 8, bsz);
        cpa16(b + ST_BLO + d0, g_wlo + bxoff,     bsz);
        cpa16(b + ST_BLO + d1, g_wlo + bxoff + 8, bsz);
        CP_COMMIT();
    }

    for (int s = 0; s < NSTAGE; s++) {
        if (s + 1 < NSTAGE) {
            uint32_t b = sbase + ((s + 1) & 1) * ST_SZ;
            size_t ko = (size_t)(s + 1) * TKB;
            cpa16(b + ST_AHI + d0, g_xhi + axoff + ko,     16);
            cpa16(b + ST_AHI + d1, g_xhi + axoff + ko + 8, 16);
            cpa16(b + ST_ALO + d0, g_xlo + axoff + ko,     16);
            cpa16(b + ST_ALO + d1, g_xlo + axoff + ko + 8, 16);
            cpa16(b + ST_BHI + d0, g_whi + bxoff + ko,     bsz);
            cpa16(b + ST_BHI + d1, g_whi + bxoff + ko + 8, bsz);
            cpa16(b + ST_BLO + d0, g_wlo + bxoff + ko,     bsz);
            cpa16(b + ST_BLO + d1, g_wlo + bxoff + ko + 8, bsz);
            CP_COMMIT();
            CP_WAIT(1);          // stage s resident
        } else {
            CP_WAIT(0);
        }
        __syncthreads();

        const uint32_t buf = sbase + (s & 1) * ST_SZ;
        #pragma unroll
        for (int kh = 0; kh < 2; kh++) {
            uint32_t af[4][4];   // a_hi fragments
            #pragma unroll
            for (int tm = 0; tm < 4; tm++) {
                int row = warp_m * 64 + tm * 16 + a_rl;
                ldsm4(af[tm], buf + ST_AHI + swz64(row, kh * 2 + a_cl));
            }
            uint32_t bh[2][4], bl[2][4];
            #pragma unroll
            for (int tp = 0; tp < 2; tp++) {
                int row = warp_n * 32 + tp * 16 + b_rl;
                uint32_t off = swz64(row, kh * 2 + b_cl);
                ldsm4(bh[tp], buf + ST_BHI + off);
                ldsm4(bl[tp], buf + ST_BLO + off);
            }
            // a_hi*b_hi + a_hi*b_lo
            #pragma unroll
            for (int tm = 0; tm < 4; tm++)
                #pragma unroll
                for (int tn = 0; tn < 4; tn++) {
                    mma16816(acc[tm][tn], af[tm],
                             bh[tn >> 1][(tn & 1) * 2], bh[tn >> 1][(tn & 1) * 2 + 1]);
                    mma16816(acc[tm][tn], af[tm],
                             bl[tn >> 1][(tn & 1) * 2], bl[tn >> 1][(tn & 1) * 2 + 1]);
                }
            // a_lo*b_hi (reuse af registers)
            #pragma unroll
            for (int tm = 0; tm < 4; tm++) {
                int row = warp_m * 64 + tm * 16 + a_rl;
                ldsm4(af[tm], buf + ST_ALO + swz64(row, kh * 2 + a_cl));
            }
            #pragma unroll
            for (int tm = 0; tm < 4; tm++)
                #pragma unroll
                for (int tn = 0; tn < 4; tn++)
                    mma16816(acc[tm][tn], af[tm],
                             bh[tn >> 1][(tn & 1) * 2], bh[tn >> 1][(tn & 1) * 2 + 1]);
        }
        __syncthreads();   // compute done before next prefetch overwrites buf
    }

    // ---- epilogue: clip to [-1,1], * xlen, store ----
    const int qrow = lane >> 2;          // 0..7
    const int qcol = (lane & 3) * 2;     // 0,2,4,6
    #pragma unroll
    for (int tm = 0; tm < 4; tm++) {
        int r = m0 + warp_m * 64 + tm * 16 + qrow;
        float xl0 = g_xlen[r];
        float xl1 = g_xlen[r + 8];
        float* po0 = out + (size_t)r * C_DIM;
        float* po1 = out + (size_t)(r + 8) * C_DIM;
        #pragma unroll
        for (int tn = 0; tn < 4; tn++) {
            int col = n0 + warp_n * 32 + tn * 8 + qcol;
            if (col < C_DIM) {   // col even, C_DIM even => col+1 in range
                float2 v0, v1;
                v0.x = fminf(1.f, fmaxf(-1.f, acc[tm][tn][0])) * xl0;
                v0.y = fminf(1.f, fmaxf(-1.f, acc[tm][tn][1])) * xl0;
                v1.x = fminf(1.f, fmaxf(-1.f, acc[tm][tn][2])) * xl1;
                v1.y = fminf(1.f, fmaxf(-1.f, acc[tm][tn][3])) * xl1;
                *reinterpret_cast<float2*>(po0 + col) = v0;
                *reinterpret_cast<float2*>(po1 + col) = v1;
            }
        }
    }
}

// ---------------------------------------------------------------------------
// Margin fix-up at label positions only (512 elements)
// ---------------------------------------------------------------------------
__global__ void fixup_kernel(const int* __restrict__ y, float* __restrict__ out) {
    int b = blockIdx.x * blockDim.x + threadIdx.x;
    if (b >= B_DIM) return;
    int c = y[b];
    float xl   = g_xlen[b];
    size_t idx = (size_t)b * C_DIM + c;
    float feat = out[idx];
    float cosv = fminf(1.f, fmaxf(-1.f, feat / xl));
    float c2   = cosv * cosv;
    float cosm = 8.f * c2 * c2 - 8.f * c2 + 1.f;                   // cos(4t)
    float kf   = floorf(4.f * acosf(cosv) * 0.3183098861837907f);  // floor(4t/pi)
    float sign = (((int)kf) & 1) ? -1.f : 1.f;
    float phi  = sign * cosm - 2.f * kf;
    out[idx]   = feat + (phi * xl - feat) * (1.f / 1001.f);
}

// ---------------------------------------------------------------------------
extern "C" void kernel_launch(void* const* d_in, const int* in_sizes, int n_in,
                              void* d_out, int out_size) {
    const float* x = (const float*)d_in[0];   // (512, 256)
    const float* w = (const float*)d_in[1];   // (100000, 256)
    const int*   y = (const int*)d_in[2];     // (512,)
    float* out = (float*)d_out;               // (512, 100000)

    // 1) normalize + bf16 hi/lo split, xlen
    prep_kernel<<<W_BLOCKS + X_BLOCKS, 256>>>(w, x);
    // 2) HMMA GEMM (compute_103-safe) + clip/scale epilogue
    cudaFuncSetAttribute(mma_gemm_kernel,
                         cudaFuncAttributeMaxDynamicSharedMemorySize, SM_TOTAL);
    mma_gemm_kernel<<<dim3(B_DIM / TMB, NT_N), 256, SM_TOTAL>>>(out);
    // 3) label fix-up
    fixup_kernel<<<2, 256>>>(y, out);
}

// round 14
// speedup vs baseline: 2.1777x; 1.0213x over previous
#include <cuda_runtime.h>
#include <cuda_bf16.h>
#include <cstdint>

#define B_DIM 512
#define D_DIM 256
#define C_DIM 100000
#define TMB 128
#define TNB 128
#define TKB 32
#define NSTAGE (D_DIM / TKB)            // 8 k-stages
#define NT_N ((C_DIM + TNB - 1) / TNB)  // 782

// ---------------- scratch (static __device__, no allocs) -------------------
__device__ float g_xlen[B_DIM];
__device__ __nv_bfloat16 g_xhi[B_DIM * D_DIM];
__device__ __nv_bfloat16 g_xlo[B_DIM * D_DIM];
__device__ __nv_bfloat16 g_whi[(size_t)C_DIM * D_DIM];
__device__ __nv_bfloat16 g_wlo[(size_t)C_DIM * D_DIM];

// ---------------------------------------------------------------------------
// Prepass: one warp per row; norm, normalize, split into bf16 hi+lo.
// Lane handles 8 CONTIGUOUS elements: 2x LDG.128 in, 2x STG.128 out
// (round-7 version used 16 scalar 2B stores -> L1-bound at DRAM=33%).
// ---------------------------------------------------------------------------
#define W_BLOCKS ((C_DIM + 7) / 8)   // 12500
#define X_BLOCKS ((B_DIM + 7) / 8)   // 64

__device__ __forceinline__ uint32_t pack_bf16x2(__nv_bfloat16 a, __nv_bfloat16 b) {
    __nv_bfloat162 t = __halves2bfloat162(a, b);
    return *reinterpret_cast<uint32_t*>(&t);
}

__global__ void prep_kernel(const float* __restrict__ w,
                            const float* __restrict__ x) {
    int lane  = threadIdx.x & 31;
    int wslot = (blockIdx.x * blockDim.x + threadIdx.x) >> 5;
    bool is_w = blockIdx.x < W_BLOCKS;
    int row   = is_w ? wslot : (wslot - W_BLOCKS * 8);
    int nrows = is_w ? C_DIM : B_DIM;
    if (row >= nrows) return;

    const float* base = is_w ? (w + (size_t)row * D_DIM)
                             : (x + (size_t)row * D_DIM);
    const float4* p = reinterpret_cast<const float4*>(base);
    float4 v0 = p[lane * 2];        // elements lane*8 .. +3
    float4 v1 = p[lane * 2 + 1];    // elements lane*8+4 .. +7
    float s = v0.x*v0.x + v0.y*v0.y + v0.z*v0.z + v0.w*v0.w
            + v1.x*v1.x + v1.y*v1.y + v1.z*v1.z + v1.w*v1.w;
    #pragma unroll
    for (int o = 16; o > 0; o >>= 1) s += __shfl_xor_sync(0xffffffffu, s, o);

    float rinv = rsqrtf(s);
    if (!is_w && lane == 0) g_xlen[row] = sqrtf(s);

    float vals[8] = {v0.x, v0.y, v0.z, v0.w, v1.x, v1.y, v1.z, v1.w};
    __nv_bfloat16 h[8], l[8];
    #pragma unroll
    for (int i = 0; i < 8; i++) {
        float v = vals[i] * rinv;
        h[i] = __float2bfloat16(v);
        l[i] = __float2bfloat16(v - __bfloat162float(h[i]));
    }
    uint4 ph = make_uint4(pack_bf16x2(h[0], h[1]), pack_bf16x2(h[2], h[3]),
                          pack_bf16x2(h[4], h[5]), pack_bf16x2(h[6], h[7]));
    uint4 pl = make_uint4(pack_bf16x2(l[0], l[1]), pack_bf16x2(l[2], l[3]),
                          pack_bf16x2(l[4], l[5]), pack_bf16x2(l[6], l[7]));
    __nv_bfloat16* hi = is_w ? g_whi : g_xhi;
    __nv_bfloat16* lo = is_w ? g_wlo : g_xlo;
    size_t off = (size_t)row * D_DIM + lane * 8;   // 16B-aligned
    *reinterpret_cast<uint4*>(hi + off) = ph;
    *reinterpret_cast<uint4*>(lo + off) = pl;
}

// ---------------------------------------------------------------------------
// Arch-portable tensor path (compute_103-safe): ldmatrix + mma.sync bf16.
// ---------------------------------------------------------------------------
__device__ __forceinline__ uint32_t smem_u32(const void* p) {
    uint32_t a;
    asm("{ .reg .u64 t; cvta.to.shared.u64 t, %1; cvt.u32.u64 %0, t; }"
        : "=r"(a) : "l"(p));
    return a;
}
__device__ __forceinline__ void ldsm4(uint32_t* r, uint32_t addr) {
    asm volatile("ldmatrix.sync.aligned.m8n8.x4.shared.b16 {%0,%1,%2,%3}, [%4];"
                 : "=r"(r[0]), "=r"(r[1]), "=r"(r[2]), "=r"(r[3]) : "r"(addr));
}
__device__ __forceinline__ void mma16816(float* c, const uint32_t* a,
                                         uint32_t b0, uint32_t b1) {
    asm volatile(
        "mma.sync.aligned.m16n8k16.row.col.f32.bf16.bf16.f32 "
        "{%0,%1,%2,%3}, {%4,%5,%6,%7}, {%8,%9}, {%0,%1,%2,%3};"
        : "+f"(c[0]), "+f"(c[1]), "+f"(c[2]), "+f"(c[3])
        : "r"(a[0]), "r"(a[1]), "r"(a[2]), "r"(a[3]), "r"(b0), "r"(b1));
}
__device__ __forceinline__ void cpa16(uint32_t dst, const void* src, int sz) {
    asm volatile("cp.async.ca.shared.global [%0], [%1], 16, %2;"
                 :: "r"(dst), "l"(src), "r"(sz));
}
#define CP_COMMIT() asm volatile("cp.async.commit_group;" ::: "memory")
#define CP_WAIT1()  asm volatile("cp.async.wait_group 1;" ::: "memory")
#define CP_WAIT0()  asm volatile("cp.async.wait_group 0;" ::: "memory")

// 64B-row swizzle: phys = row*64 + ((chunk16 ^ ((row>>1)&3)) * 16)  (conflict-free)
__device__ __forceinline__ uint32_t swz64(int row, int chunk) {
    return (uint32_t)(row * 64 + ((chunk ^ ((row >> 1) & 3)) << 4));
}

// SMEM stage layout: Ahi | Alo | Bhi | Blo, each 128 rows x 64B = 8 KB
#define ST_AHI 0
#define ST_ALO 8192
#define ST_BHI 16384
#define ST_BLO 24576
#define ST_SZ  32768
#define NBUF   3
#define SM_TOTAL (NBUF * ST_SZ)   // 96 KB x 2 CTAs = 192 KB <= 227 KB

// ---------------------------------------------------------------------------
// GEMM: cos[b,c] via 3-term bf16 split (ah*bh + ah*bl + al*bh), fp32 acc.
// CTA 128x128x32, 8 warps 2(M)x4(N), warp tile 64x32, m16n8k16 HMMA.
// 3-stage cp.async pipeline, ONE barrier per stage:
//   wait(s) -> barrier (proves buf (s-1)%3 compute done everywhere)
//   -> prefetch s+2 into (s+2)%3 == (s-1)%3 -> compute buf s%3.
// Epilogue: clip * xlen.
// ---------------------------------------------------------------------------
__global__ __launch_bounds__(256, 2)
void mma_gemm_kernel(float* __restrict__ out) {
    extern __shared__ char smem[];
    const uint32_t sbase = smem_u32(smem);

    const int tid    = threadIdx.x;
    const int lane   = tid & 31;
    const int wid    = tid >> 5;
    const int warp_m = wid & 1;        // 0..1 -> 64 rows
    const int warp_n = wid >> 1;       // 0..3 -> 32 cols
    const int m0     = blockIdx.x * TMB;   // fast dim: 4 CTAs share B tile in L2
    const int n0     = blockIdx.y * TNB;

    // ---- cp.async store-side mapping: row = tid>>1, two 16B chunks ----
    const int srow = tid >> 1;
    const int sc0  = (tid & 1) * 2;
    const uint32_t d0 = swz64(srow, sc0);
    const uint32_t d1 = swz64(srow, sc0 + 1);
    const size_t axoff = (size_t)(m0 + srow) * D_DIM + sc0 * 8;
    const int gn   = n0 + srow;
    const int bsz  = (gn < C_DIM) ? 16 : 0;      // 0 => cp.async zero-fill
    const size_t bxoff = (size_t)((gn < C_DIM) ? gn : 0) * D_DIM + sc0 * 8;

    // ---- ldmatrix lane mappings (canonical m16n8k16 fragments) ----
    const int a_rl = (lane & 15);
    const int a_cl = (lane >> 4);
    const int b_rl = (lane & 7) + ((lane >> 4) & 1) * 8;
    const int b_cl = (lane >> 3) & 1;

    float acc[4][4][4];
    #pragma unroll
    for (int i = 0; i < 4; i++)
        #pragma unroll
        for (int j = 0; j < 4; j++)
            #pragma unroll
            for (int r = 0; r < 4; r++) acc[i][j][r] = 0.f;

    auto issue_stage = [&](int s, uint32_t b) {
        size_t ko = (size_t)s * TKB;
        cpa16(b + ST_AHI + d0, g_xhi + axoff + ko,     16);
        cpa16(b + ST_AHI + d1, g_xhi + axoff + ko + 8, 16);
        cpa16(b + ST_ALO + d0, g_xlo + axoff + ko,     16);
        cpa16(b + ST_ALO + d1, g_xlo + axoff + ko + 8, 16);
        cpa16(b + ST_BHI + d0, g_whi + bxoff + ko,     bsz);
        cpa16(b + ST_BHI + d1, g_whi + bxoff + ko + 8, bsz);
        cpa16(b + ST_BLO + d0, g_wlo + bxoff + ko,     bsz);
        cpa16(b + ST_BLO + d1, g_wlo + bxoff + ko + 8, bsz);
        CP_COMMIT();
    };

    // ---- prologue: stages 0 and 1 in flight ----
    issue_stage(0, sbase);
    issue_stage(1, sbase + ST_SZ);

    for (int s = 0; s < NSTAGE; s++) {
        if (s < NSTAGE - 1) { CP_WAIT1(); } else { CP_WAIT0(); }
        __syncthreads();

        if (s + 2 < NSTAGE)
            issue_stage(s + 2, sbase + ((s + 2) % NBUF) * ST_SZ);

        const uint32_t buf = sbase + (s % NBUF) * ST_SZ;
        #pragma unroll
        for (int kh = 0; kh < 2; kh++) {
            uint32_t af[4][4];   // a_hi fragments
            #pragma unroll
            for (int tm = 0; tm < 4; tm++) {
                int row = warp_m * 64 + tm * 16 + a_rl;
                ldsm4(af[tm], buf + ST_AHI + swz64(row, kh * 2 + a_cl));
            }
            uint32_t bh[2][4], bl[2][4];
            #pragma unroll
            for (int tp = 0; tp < 2; tp++) {
                int row = warp_n * 32 + tp * 16 + b_rl;
                uint32_t off = swz64(row, kh * 2 + b_cl);
                ldsm4(bh[tp], buf + ST_BHI + off);
                ldsm4(bl[tp], buf + ST_BLO + off);
            }
            // a_hi*b_hi + a_hi*b_lo
            #pragma unroll
            for (int tm = 0; tm < 4; tm++)
                #pragma unroll
                for (int tn = 0; tn < 4; tn++) {
                    mma16816(acc[tm][tn], af[tm],
                             bh[tn >> 1][(tn & 1) * 2], bh[tn >> 1][(tn & 1) * 2 + 1]);
                    mma16816(acc[tm][tn], af[tm],
                             bl[tn >> 1][(tn & 1) * 2], bl[tn >> 1][(tn & 1) * 2 + 1]);
                }
            // a_lo*b_hi (reuse af registers)
            #pragma unroll
            for (int tm = 0; tm < 4; tm++) {
                int row = warp_m * 64 + tm * 16 + a_rl;
                ldsm4(af[tm], buf + ST_ALO + swz64(row, kh * 2 + a_cl));
            }
            #pragma unroll
            for (int tm = 0; tm < 4; tm++)
                #pragma unroll
                for (int tn = 0; tn < 4; tn++)
                    mma16816(acc[tm][tn], af[tm],
                             bh[tn >> 1][(tn & 1) * 2], bh[tn >> 1][(tn & 1) * 2 + 1]);
        }
    }

    // ---- epilogue: clip to [-1,1], * xlen, store ----
    const int qrow = lane >> 2;          // 0..7
    const int qcol = (lane & 3) * 2;     // 0,2,4,6
    #pragma unroll
    for (int tm = 0; tm < 4; tm++) {
        int r = m0 + warp_m * 64 + tm * 16 + qrow;
        float xl0 = g_xlen[r];
        float xl1 = g_xlen[r + 8];
        float* po0 = out + (size_t)r * C_DIM;
        float* po1 = out + (size_t)(r + 8) * C_DIM;
        #pragma unroll
        for (int tn = 0; tn < 4; tn++) {
            int col = n0 + warp_n * 32 + tn * 8 + qcol;
            if (col < C_DIM) {   // col even, C_DIM even => col+1 in range
                float2 v0, v1;
                v0.x = fminf(1.f, fmaxf(-1.f, acc[tm][tn][0])) * xl0;
                v0.y = fminf(1.f, fmaxf(-1.f, acc[tm][tn][1])) * xl0;
                v1.x = fminf(1.f, fmaxf(-1.f, acc[tm][tn][2])) * xl1;
                v1.y = fminf(1.f, fmaxf(-1.f, acc[tm][tn][3])) * xl1;
                *reinterpret_cast<float2*>(po0 + col) = v0;
                *reinterpret_cast<float2*>(po1 + col) = v1;
            }
        }
    }
}

// ---------------------------------------------------------------------------
// Margin fix-up at label positions only (512 elements)
// ---------------------------------------------------------------------------
__global__ void fixup_kernel(const int* __restrict__ y, float* __restrict__ out) {
    int b = blockIdx.x * blockDim.x + threadIdx.x;
    if (b >= B_DIM) return;
    int c = y[b];
    float xl   = g_xlen[b];
    size_t idx = (size_t)b * C_DIM + c;
    float feat = out[idx];
    float cosv = fminf(1.f, fmaxf(-1.f, feat / xl));
    float c2   = cosv * cosv;
    float cosm = 8.f * c2 * c2 - 8.f * c2 + 1.f;                   // cos(4t)
    float kf   = floorf(4.f * acosf(cosv) * 0.3183098861837907f);  // floor(4t/pi)
    float sign = (((int)kf) & 1) ? -1.f : 1.f;
    float phi  = sign * cosm - 2.f * kf;
    out[idx]   = feat + (phi * xl - feat) * (1.f / 1001.f);
}

// ---------------------------------------------------------------------------
extern "C" void kernel_launch(void* const* d_in, const int* in_sizes, int n_in,
                              void* d_out, int out_size) {
    const float* x = (const float*)d_in[0];   // (512, 256)
    const float* w = (const float*)d_in[1];   // (100000, 256)
    const int*   y = (const int*)d_in[2];     // (512,)
    float* out = (float*)d_out;               // (512, 100000)

    // 1) normalize + bf16 hi/lo split, xlen (vectorized stores)
    prep_kernel<<<W_BLOCKS + X_BLOCKS, 256>>>(w, x);
    // 2) HMMA GEMM, 3-stage cp.async pipeline + clip/scale epilogue
    cudaFuncSetAttribute(mma_gemm_kernel,
                         cudaFuncAttributeMaxDynamicSharedMemorySize, SM_TOTAL);
    mma_gemm_kernel<<<dim3(B_DIM / TMB, NT_N), 256, SM_TOTAL>>>(out);
    // 3) label fix-up
    fixup_kernel<<<2, 256>>>(y, out);
}